// round 11
// baseline (speedup 1.0000x reference)
#include <cuda_runtime.h>
#include <cuda_fp16.h>
#include <math.h>
#include <stdint.h>

#define NBH 128           // B*H
#define NQ 4
#define DIM 128
#define SEQ 4096
#define NSPLIT 8
#define KEYS_PER_SPLIT 1024
#define NTHREADS 256
#define NOUT (NBH * NQ * DIM)        // 65536
#define NLSE (NBH * NQ)              // 512
#define SCALE_LOG2E 0.12751649736461817f   // (1/sqrt(128)) * log2(e)

typedef unsigned long long ull;

// per-split partials — each slot written exactly once per launch (no zeroing, no atomics)
__device__ float g_part[NSPLIT * NOUT];
__device__ float g_pse[NSPLIT * NLSE];

// ---- packed f32x2 helpers (ptxas won't auto-fuse; PTX required) ----
__device__ __forceinline__ void fma2(ull& d, ull a, ull b) {
    asm("fma.rn.f32x2 %0, %1, %2, %0;" : "+l"(d) : "l"(a), "l"(b));
}
__device__ __forceinline__ ull mul2(ull a, ull b) {
    ull r; asm("mul.rn.f32x2 %0, %1, %2;" : "=l"(r) : "l"(a), "l"(b)); return r;
}
__device__ __forceinline__ ull pack2(float lo, float hi) {
    ull r; asm("mov.b64 %0, {%1, %2};" : "=l"(r) : "f"(lo), "f"(hi)); return r;
}
__device__ __forceinline__ void unpack2(ull v, float& lo, float& hi) {
    asm("mov.b64 {%0, %1}, %2;" : "=f"(lo), "=f"(hi) : "l"(v));
}
__device__ __forceinline__ ull pack2u(unsigned lo, unsigned hi) {
    ull r; asm("mov.b64 %0, {%1, %2};" : "=l"(r) : "r"(lo), "r"(hi)); return r;
}
__device__ __forceinline__ float ex2a(float x) {
    float r; asm("ex2.approx.f32 %0, %1;" : "=f"(r) : "f"(x)); return r;
}

// fp32 inputs; 16 lanes/key, 8 dims/lane, 2 keys per warp-iteration.
// Register double-buffered K/V loads: 16 LDG.128 outstanding per warp.
__global__ void __launch_bounds__(NTHREADS, 2) attn_f32(
    const float* __restrict__ qg,
    const float* __restrict__ kA, const float* __restrict__ vA,
    const float* __restrict__ kB, const float* __restrict__ vB)
{
    const int bh = blockIdx.x, split = blockIdx.y;
    const float* kp; const float* vp; int s0;
    if (split < NSPLIT / 2) { kp = kA; vp = vA; s0 = split * KEYS_PER_SPLIT; }
    else                    { kp = kB; vp = vB; s0 = (split - NSPLIT / 2) * KEYS_PER_SPLIT; }
    const size_t base = (size_t)bh * SEQ * DIM;
    kp += base; vp += base;

    const int tid = threadIdx.x, lane = tid & 31, w = tid >> 5;
    const int g   = lane >> 4;       // 2 key groups per warp
    const int sub = lane & 15;       // 16 lanes per key
    const int dbase = sub << 3;      // 8 dims per lane

    // q: 4 rows x 8 dims, packed f32x2
    ull q2[NQ][4];
    {
        const float* qb = qg + (size_t)bh * NQ * DIM + dbase;
        #pragma unroll
        for (int qi = 0; qi < NQ; qi++) {
            uint4 a = __ldg(reinterpret_cast<const uint4*>(qb + qi * DIM));
            uint4 b = __ldg(reinterpret_cast<const uint4*>(qb + qi * DIM + 4));
            q2[qi][0] = pack2u(a.x, a.y);
            q2[qi][1] = pack2u(a.z, a.w);
            q2[qi][2] = pack2u(b.x, b.y);
            q2[qi][3] = pack2u(b.z, b.w);
        }
    }

    ull acc2[NQ][4];
    #pragma unroll
    for (int qi = 0; qi < NQ; qi++)
        #pragma unroll
        for (int j = 0; j < 4; j++) acc2[qi][j] = 0ull;
    float se[NQ] = {0.f, 0.f, 0.f, 0.f};

    const int kbase = s0 + w * 128 + g;   // warp owns 128 keys
    const float* krow = kp + (size_t)kbase * DIM + dbase;
    const float* vrow = vp + (size_t)kbase * DIM + dbase;

    // prologue loads (iteration 0)
    uint4 ka = __ldcs(reinterpret_cast<const uint4*>(krow));
    uint4 kb = __ldcs(reinterpret_cast<const uint4*>(krow + 4));
    uint4 va = __ldcs(reinterpret_cast<const uint4*>(vrow));
    uint4 vb = __ldcs(reinterpret_cast<const uint4*>(vrow + 4));

    #pragma unroll 2
    for (int i = 0; i < 64; i++) {
        // prefetch iteration i+1 while computing on i
        uint4 nka, nkb, nva, nvb;
        if (i < 63) {
            const float* nk = krow + (size_t)((i + 1) << 1) * DIM;
            const float* nv = vrow + (size_t)((i + 1) << 1) * DIM;
            nka = __ldcs(reinterpret_cast<const uint4*>(nk));
            nkb = __ldcs(reinterpret_cast<const uint4*>(nk + 4));
            nva = __ldcs(reinterpret_cast<const uint4*>(nv));
            nvb = __ldcs(reinterpret_cast<const uint4*>(nv + 4));
        }

        ull k2[4] = {pack2u(ka.x, ka.y), pack2u(ka.z, ka.w),
                     pack2u(kb.x, kb.y), pack2u(kb.z, kb.w)};

        float sc[NQ];
        #pragma unroll
        for (int qi = 0; qi < NQ; qi++) {
            ull c = mul2(q2[qi][0], k2[0]);
            fma2(c, q2[qi][1], k2[1]);
            fma2(c, q2[qi][2], k2[2]);
            fma2(c, q2[qi][3], k2[3]);
            float lo, hi; unpack2(c, lo, hi);
            sc[qi] = lo + hi;
        }

        #pragma unroll
        for (int m = 1; m < 16; m <<= 1)
            #pragma unroll
            for (int qi = 0; qi < NQ; qi++)
                sc[qi] += __shfl_xor_sync(0xffffffffu, sc[qi], m);

        ull v2[4] = {pack2u(va.x, va.y), pack2u(va.z, va.w),
                     pack2u(vb.x, vb.y), pack2u(vb.z, vb.w)};

        #pragma unroll
        for (int qi = 0; qi < NQ; qi++) {
            float p = ex2a(sc[qi] * SCALE_LOG2E);
            se[qi] += p;
            ull pp = pack2(p, p);
            #pragma unroll
            for (int j = 0; j < 4; j++) fma2(acc2[qi][j], v2[j], pp);
        }

        ka = nka; kb = nkb; va = nva; vb = nvb;
    }

    // unpack and reduce across the two key groups (xor 16)
    float af[NQ][8];
    #pragma unroll
    for (int qi = 0; qi < NQ; qi++)
        #pragma unroll
        for (int j = 0; j < 4; j++)
            unpack2(acc2[qi][j], af[qi][2 * j], af[qi][2 * j + 1]);
    #pragma unroll
    for (int qi = 0; qi < NQ; qi++) {
        #pragma unroll
        for (int d = 0; d < 8; d++)
            af[qi][d] += __shfl_xor_sync(0xffffffffu, af[qi][d], 16);
        se[qi] += __shfl_xor_sync(0xffffffffu, se[qi], 16);
    }

    __shared__ float sm[8][NQ * DIM];   // 16 KB
    __shared__ float sm_se[8][NQ];
    if (lane < 16)
        #pragma unroll
        for (int qi = 0; qi < NQ; qi++)
            #pragma unroll
            for (int d = 0; d < 8; d++)
                sm[w][qi * DIM + lane * 8 + d] = af[qi][d];
    if (lane == 0)
        #pragma unroll
        for (int qi = 0; qi < NQ; qi++) sm_se[w][qi] = se[qi];
    __syncthreads();

    // block-level tree sum, then one clean store per element (no atomics)
    float* part = g_part + (size_t)split * NOUT + bh * NQ * DIM;
    for (int o = tid; o < NQ * DIM; o += NTHREADS) {
        float sum = 0.f;
        #pragma unroll
        for (int ww = 0; ww < 8; ww++) sum += sm[ww][o];
        part[o] = sum;
    }
    if (tid < NQ) {
        float sum = 0.f;
        #pragma unroll
        for (int ww = 0; ww < 8; ww++) sum += sm_se[ww][tid];
        g_pse[split * NLSE + bh * NQ + tid] = sum;
    }
}

// Output: fp32 buffer, out_size elements.
//   [0, 65536):      out — fp32 double-rounded through fp16 (ref casts to fp16)
//   [65536, 66048):  lse (fp32)
//   [66048, out_size): zeros (harness poisons with 0xAA)
__global__ void finalize_kernel(float* out, int out_elems) {
    int i = blockIdx.x * blockDim.x + threadIdx.x;
    if (i < NOUT) {
        int bhq = i >> 7;
        float a = 0.f, s = 0.f;
        #pragma unroll
        for (int sp = 0; sp < NSPLIT; sp++) {
            a += g_part[sp * NOUT + i];
            s += g_pse[sp * NLSE + bhq];
        }
        out[i] = __half2float(__float2half(a / s));
    } else if (i < NOUT + NLSE) {
        int bhq = i - NOUT;
        float s = 0.f;
        #pragma unroll
        for (int sp = 0; sp < NSPLIT; sp++) s += g_pse[sp * NLSE + bhq];
        out[i] = logf(s);
    } else if (i < out_elems) {
        out[i] = 0.0f;
    }
}

extern "C" void kernel_launch(void* const* d_in, const int* in_sizes, int n_in,
                              void* d_out, int out_size) {
    // Proven (R9/R10): fp32 inputs, dict ordering:
    //   q, k_A, v_A, k_B_gpu(zeros), v_B_gpu(zeros), k_B_host, v_B_host
    const float* q  = reinterpret_cast<const float*>(d_in[0]);
    const float* kA = reinterpret_cast<const float*>(d_in[1]);
    const float* vA = reinterpret_cast<const float*>(d_in[2]);
    const float* kB = reinterpret_cast<const float*>(d_in[5]);
    const float* vB = reinterpret_cast<const float*>(d_in[6]);

    dim3 grid(NBH, NSPLIT);
    attn_f32<<<grid, NTHREADS>>>(q, kA, vA, kB, vB);

    int full = NOUT + NLSE;
    int cover = out_size > full ? out_size : full;
    finalize_kernel<<<(cover + 255) / 256, 256>>>(
        reinterpret_cast<float*>(d_out), out_size);
}

// round 12
// speedup vs baseline: 1.0367x; 1.0367x over previous
#include <cuda_runtime.h>
#include <cuda_fp16.h>
#include <math.h>
#include <stdint.h>

#define NBH 128           // B*H
#define NQ 4
#define DIM 128
#define SEQ 4096
#define NSPLIT 8
#define KEYS_PER_SPLIT 1024
#define NTHREADS 256
#define NOUT (NBH * NQ * DIM)        // 65536
#define NLSE (NBH * NQ)              // 512
#define SCALE_LOG2E 0.12751649736461817f   // (1/sqrt(128)) * log2(e)

typedef unsigned long long ull;

// per-split partials — each slot written exactly once per launch (no zeroing, no atomics)
__device__ float g_part[NSPLIT * NOUT];
__device__ float g_pse[NSPLIT * NLSE];

// ---- packed f32x2 helpers (ptxas won't auto-fuse; PTX required) ----
__device__ __forceinline__ void fma2(ull& d, ull a, ull b) {
    asm("fma.rn.f32x2 %0, %1, %2, %0;" : "+l"(d) : "l"(a), "l"(b));
}
__device__ __forceinline__ ull mul2(ull a, ull b) {
    ull r; asm("mul.rn.f32x2 %0, %1, %2;" : "=l"(r) : "l"(a), "l"(b)); return r;
}
__device__ __forceinline__ ull pack2(float lo, float hi) {
    ull r; asm("mov.b64 %0, {%1, %2};" : "=l"(r) : "f"(lo), "f"(hi)); return r;
}
__device__ __forceinline__ void unpack2(ull v, float& lo, float& hi) {
    asm("mov.b64 {%0, %1}, %2;" : "=f"(lo), "=f"(hi) : "l"(v));
}
__device__ __forceinline__ ull pack2u(unsigned lo, unsigned hi) {
    ull r; asm("mov.b64 %0, {%1, %2};" : "=l"(r) : "r"(lo), "r"(hi)); return r;
}
__device__ __forceinline__ float ex2a(float x) {
    float r; asm("ex2.approx.f32 %0, %1;" : "=f"(r) : "f"(x)); return r;
}

// fp32 inputs; 16 lanes/key, 8 dims/lane, 2 keys per warp-iteration.
// R10's proven mainloop (plain ldcs + unroll 2, ptxas schedules the loads).
__global__ void __launch_bounds__(NTHREADS, 2) attn_f32(
    const float* __restrict__ qg,
    const float* __restrict__ kA, const float* __restrict__ vA,
    const float* __restrict__ kB, const float* __restrict__ vB)
{
    const int bh = blockIdx.x, split = blockIdx.y;
    const float* kp; const float* vp; int s0;
    if (split < NSPLIT / 2) { kp = kA; vp = vA; s0 = split * KEYS_PER_SPLIT; }
    else                    { kp = kB; vp = vB; s0 = (split - NSPLIT / 2) * KEYS_PER_SPLIT; }
    const size_t base = (size_t)bh * SEQ * DIM;
    kp += base; vp += base;

    const int tid = threadIdx.x, lane = tid & 31, w = tid >> 5;
    const int g   = lane >> 4;       // 2 key groups per warp
    const int sub = lane & 15;       // 16 lanes per key
    const int dbase = sub << 3;      // 8 dims per lane

    // q: 4 rows x 8 dims, packed f32x2
    ull q2[NQ][4];
    {
        const float* qb = qg + (size_t)bh * NQ * DIM + dbase;
        #pragma unroll
        for (int qi = 0; qi < NQ; qi++) {
            uint4 a = __ldg(reinterpret_cast<const uint4*>(qb + qi * DIM));
            uint4 b = __ldg(reinterpret_cast<const uint4*>(qb + qi * DIM + 4));
            q2[qi][0] = pack2u(a.x, a.y);
            q2[qi][1] = pack2u(a.z, a.w);
            q2[qi][2] = pack2u(b.x, b.y);
            q2[qi][3] = pack2u(b.z, b.w);
        }
    }

    ull acc2[NQ][4];
    #pragma unroll
    for (int qi = 0; qi < NQ; qi++)
        #pragma unroll
        for (int j = 0; j < 4; j++) acc2[qi][j] = 0ull;
    float se[NQ] = {0.f, 0.f, 0.f, 0.f};

    const int kbase = s0 + w * 128 + g;   // warp owns 128 keys

    #pragma unroll 2
    for (int i = 0; i < 64; i++) {
        const int s = kbase + (i << 1);
        const float* krow = kp + (size_t)s * DIM + dbase;
        const float* vrow = vp + (size_t)s * DIM + dbase;
        // streaming loads: KV has zero reuse — evict-first
        uint4 ka = __ldcs(reinterpret_cast<const uint4*>(krow));
        uint4 kb = __ldcs(reinterpret_cast<const uint4*>(krow + 4));
        uint4 va = __ldcs(reinterpret_cast<const uint4*>(vrow));
        uint4 vb = __ldcs(reinterpret_cast<const uint4*>(vrow + 4));

        ull k2[4] = {pack2u(ka.x, ka.y), pack2u(ka.z, ka.w),
                     pack2u(kb.x, kb.y), pack2u(kb.z, kb.w)};

        // scores: 4 f32x2 FMAs per q (8 dims), then horizontal add
        float sc[NQ];
        #pragma unroll
        for (int qi = 0; qi < NQ; qi++) {
            ull c = mul2(q2[qi][0], k2[0]);
            fma2(c, q2[qi][1], k2[1]);
            fma2(c, q2[qi][2], k2[2]);
            fma2(c, q2[qi][3], k2[3]);
            float lo, hi; unpack2(c, lo, hi);
            sc[qi] = lo + hi;
        }

        // butterfly over the 16 lanes of this key group
        #pragma unroll
        for (int m = 1; m < 16; m <<= 1)
            #pragma unroll
            for (int qi = 0; qi < NQ; qi++)
                sc[qi] += __shfl_xor_sync(0xffffffffu, sc[qi], m);

        ull v2[4] = {pack2u(va.x, va.y), pack2u(va.z, va.w),
                     pack2u(vb.x, vb.y), pack2u(vb.z, vb.w)};

        #pragma unroll
        for (int qi = 0; qi < NQ; qi++) {
            float p = ex2a(sc[qi] * SCALE_LOG2E);   // exp(s*SCALE)
            se[qi] += p;
            ull pp = pack2(p, p);
            #pragma unroll
            for (int j = 0; j < 4; j++) fma2(acc2[qi][j], v2[j], pp);
        }
    }

    // unpack and reduce across the two key groups (xor 16)
    float af[NQ][8];
    #pragma unroll
    for (int qi = 0; qi < NQ; qi++)
        #pragma unroll
        for (int j = 0; j < 4; j++)
            unpack2(acc2[qi][j], af[qi][2 * j], af[qi][2 * j + 1]);
    #pragma unroll
    for (int qi = 0; qi < NQ; qi++) {
        #pragma unroll
        for (int d = 0; d < 8; d++)
            af[qi][d] += __shfl_xor_sync(0xffffffffu, af[qi][d], 16);
        se[qi] += __shfl_xor_sync(0xffffffffu, se[qi], 16);
    }

    __shared__ float sm[8][NQ * DIM];   // 16 KB
    __shared__ float sm_se[8][NQ];
    if (lane < 16)
        #pragma unroll
        for (int qi = 0; qi < NQ; qi++)
            #pragma unroll
            for (int d = 0; d < 8; d++)
                sm[w][qi * DIM + lane * 8 + d] = af[qi][d];
    if (lane == 0)
        #pragma unroll
        for (int qi = 0; qi < NQ; qi++) sm_se[w][qi] = se[qi];
    __syncthreads();

    // block-level tree sum, then one clean store per element (no atomics)
    float* part = g_part + (size_t)split * NOUT + bh * NQ * DIM;
    for (int o = tid; o < NQ * DIM; o += NTHREADS) {
        float sum = 0.f;
        #pragma unroll
        for (int ww = 0; ww < 8; ww++) sum += sm[ww][o];
        part[o] = sum;
    }
    if (tid < NQ) {
        float sum = 0.f;
        #pragma unroll
        for (int ww = 0; ww < 8; ww++) sum += sm_se[ww][tid];
        g_pse[split * NLSE + bh * NQ + tid] = sum;
    }
}

// Output: fp32 buffer, out_size elements.
//   [0, 65536):      out — fp32 double-rounded through fp16 (ref casts to fp16)
//   [65536, 66048):  lse (fp32)
//   [66048, out_size): zeros (harness poisons with 0xAA)
__global__ void finalize_kernel(float* out, int out_elems) {
    int i = blockIdx.x * blockDim.x + threadIdx.x;
    if (i < NOUT) {
        int bhq = i >> 7;
        float a = 0.f, s = 0.f;
        #pragma unroll
        for (int sp = 0; sp < NSPLIT; sp++) {
            a += g_part[sp * NOUT + i];
            s += g_pse[sp * NLSE + bhq];
        }
        out[i] = __half2float(__float2half(a / s));
    } else if (i < NOUT + NLSE) {
        int bhq = i - NOUT;
        float s = 0.f;
        #pragma unroll
        for (int sp = 0; sp < NSPLIT; sp++) s += g_pse[sp * NLSE + bhq];
        out[i] = logf(s);
    } else if (i < out_elems) {
        out[i] = 0.0f;
    }
}

extern "C" void kernel_launch(void* const* d_in, const int* in_sizes, int n_in,
                              void* d_out, int out_size) {
    // Proven (R9/R10): fp32 inputs, dict ordering:
    //   q, k_A, v_A, k_B_gpu(zeros), v_B_gpu(zeros), k_B_host, v_B_host
    const float* q  = reinterpret_cast<const float*>(d_in[0]);
    const float* kA = reinterpret_cast<const float*>(d_in[1]);
    const float* vA = reinterpret_cast<const float*>(d_in[2]);
    const float* kB = reinterpret_cast<const float*>(d_in[5]);
    const float* vB = reinterpret_cast<const float*>(d_in[6]);

    dim3 grid(NBH, NSPLIT);
    attn_f32<<<grid, NTHREADS>>>(q, kA, vA, kB, vB);

    int full = NOUT + NLSE;
    int cover = out_size > full ? out_size : full;
    finalize_kernel<<<(cover + 255) / 256, 256>>>(
        reinterpret_cast<float*>(d_out), out_size);
}

// round 13
// speedup vs baseline: 1.0857x; 1.0473x over previous
#include <cuda_runtime.h>
#include <cuda_fp16.h>
#include <math.h>
#include <stdint.h>

#define NBH 128           // B*H
#define NQ 4
#define DIM 128
#define SEQ 4096
#define NSPLIT 16         // 16 splits of 512 keys over the 8192 combined keys
#define KEYS_PER_SPLIT 512
#define NTHREADS 256
#define NOUT (NBH * NQ * DIM)        // 65536
#define NLSE (NBH * NQ)              // 512
#define SCALE_LOG2E 0.12751649736461817f   // (1/sqrt(128)) * log2(e)

typedef unsigned long long ull;

// per-split partials — each slot written exactly once per launch (no zeroing, no atomics)
__device__ float g_part[NSPLIT * NOUT];   // 4 MB
__device__ float g_pse[NSPLIT * NLSE];

// ---- packed f32x2 helpers (ptxas won't auto-fuse; PTX required) ----
__device__ __forceinline__ void fma2(ull& d, ull a, ull b) {
    asm("fma.rn.f32x2 %0, %1, %2, %0;" : "+l"(d) : "l"(a), "l"(b));
}
__device__ __forceinline__ ull mul2(ull a, ull b) {
    ull r; asm("mul.rn.f32x2 %0, %1, %2;" : "=l"(r) : "l"(a), "l"(b)); return r;
}
__device__ __forceinline__ ull pack2(float lo, float hi) {
    ull r; asm("mov.b64 %0, {%1, %2};" : "=l"(r) : "f"(lo), "f"(hi)); return r;
}
__device__ __forceinline__ void unpack2(ull v, float& lo, float& hi) {
    asm("mov.b64 {%0, %1}, %2;" : "=f"(lo), "=f"(hi) : "l"(v));
}
__device__ __forceinline__ ull pack2u(unsigned lo, unsigned hi) {
    ull r; asm("mov.b64 %0, {%1, %2};" : "=l"(r) : "r"(lo), "r"(hi)); return r;
}
__device__ __forceinline__ float ex2a(float x) {
    float r; asm("ex2.approx.f32 %0, %1;" : "=f"(r) : "f"(x)); return r;
}

// fp32 inputs; 16 lanes/key, 8 dims/lane, 2 keys per warp-iteration.
// R10's proven mainloop (plain ldcs + unroll 2); 64 keys per warp.
__global__ void __launch_bounds__(NTHREADS, 2) attn_f32(
    const float* __restrict__ qg,
    const float* __restrict__ kA, const float* __restrict__ vA,
    const float* __restrict__ kB, const float* __restrict__ vB)
{
    const int bh = blockIdx.x, split = blockIdx.y;
    const float* kp; const float* vp; int s0;
    if (split < NSPLIT / 2) { kp = kA; vp = vA; s0 = split * KEYS_PER_SPLIT; }
    else                    { kp = kB; vp = vB; s0 = (split - NSPLIT / 2) * KEYS_PER_SPLIT; }
    const size_t base = (size_t)bh * SEQ * DIM;
    kp += base; vp += base;

    const int tid = threadIdx.x, lane = tid & 31, w = tid >> 5;
    const int g   = lane >> 4;       // 2 key groups per warp
    const int sub = lane & 15;       // 16 lanes per key
    const int dbase = sub << 3;      // 8 dims per lane

    // q: 4 rows x 8 dims, packed f32x2
    ull q2[NQ][4];
    {
        const float* qb = qg + (size_t)bh * NQ * DIM + dbase;
        #pragma unroll
        for (int qi = 0; qi < NQ; qi++) {
            uint4 a = __ldg(reinterpret_cast<const uint4*>(qb + qi * DIM));
            uint4 b = __ldg(reinterpret_cast<const uint4*>(qb + qi * DIM + 4));
            q2[qi][0] = pack2u(a.x, a.y);
            q2[qi][1] = pack2u(a.z, a.w);
            q2[qi][2] = pack2u(b.x, b.y);
            q2[qi][3] = pack2u(b.z, b.w);
        }
    }

    ull acc2[NQ][4];
    #pragma unroll
    for (int qi = 0; qi < NQ; qi++)
        #pragma unroll
        for (int j = 0; j < 4; j++) acc2[qi][j] = 0ull;
    float se[NQ] = {0.f, 0.f, 0.f, 0.f};

    const int kbase = s0 + w * 64 + g;   // warp owns 64 keys

    #pragma unroll 2
    for (int i = 0; i < 32; i++) {
        const int s = kbase + (i << 1);
        const float* krow = kp + (size_t)s * DIM + dbase;
        const float* vrow = vp + (size_t)s * DIM + dbase;
        // streaming loads: KV has zero reuse — evict-first
        uint4 ka = __ldcs(reinterpret_cast<const uint4*>(krow));
        uint4 kb = __ldcs(reinterpret_cast<const uint4*>(krow + 4));
        uint4 va = __ldcs(reinterpret_cast<const uint4*>(vrow));
        uint4 vb = __ldcs(reinterpret_cast<const uint4*>(vrow + 4));

        ull k2[4] = {pack2u(ka.x, ka.y), pack2u(ka.z, ka.w),
                     pack2u(kb.x, kb.y), pack2u(kb.z, kb.w)};

        // scores: 4 f32x2 FMAs per q (8 dims), then horizontal add
        float sc[NQ];
        #pragma unroll
        for (int qi = 0; qi < NQ; qi++) {
            ull c = mul2(q2[qi][0], k2[0]);
            fma2(c, q2[qi][1], k2[1]);
            fma2(c, q2[qi][2], k2[2]);
            fma2(c, q2[qi][3], k2[3]);
            float lo, hi; unpack2(c, lo, hi);
            sc[qi] = lo + hi;
        }

        // butterfly over the 16 lanes of this key group
        #pragma unroll
        for (int m = 1; m < 16; m <<= 1)
            #pragma unroll
            for (int qi = 0; qi < NQ; qi++)
                sc[qi] += __shfl_xor_sync(0xffffffffu, sc[qi], m);

        ull v2[4] = {pack2u(va.x, va.y), pack2u(va.z, va.w),
                     pack2u(vb.x, vb.y), pack2u(vb.z, vb.w)};

        #pragma unroll
        for (int qi = 0; qi < NQ; qi++) {
            float p = ex2a(sc[qi] * SCALE_LOG2E);   // exp(s*SCALE)
            se[qi] += p;
            ull pp = pack2(p, p);
            #pragma unroll
            for (int j = 0; j < 4; j++) fma2(acc2[qi][j], v2[j], pp);
        }
    }

    // unpack and reduce across the two key groups (xor 16)
    float af[NQ][8];
    #pragma unroll
    for (int qi = 0; qi < NQ; qi++)
        #pragma unroll
        for (int j = 0; j < 4; j++)
            unpack2(acc2[qi][j], af[qi][2 * j], af[qi][2 * j + 1]);
    #pragma unroll
    for (int qi = 0; qi < NQ; qi++) {
        #pragma unroll
        for (int d = 0; d < 8; d++)
            af[qi][d] += __shfl_xor_sync(0xffffffffu, af[qi][d], 16);
        se[qi] += __shfl_xor_sync(0xffffffffu, se[qi], 16);
    }

    __shared__ float sm[8][NQ * DIM];   // 16 KB
    __shared__ float sm_se[8][NQ];
    if (lane < 16)
        #pragma unroll
        for (int qi = 0; qi < NQ; qi++)
            #pragma unroll
            for (int d = 0; d < 8; d++)
                sm[w][qi * DIM + lane * 8 + d] = af[qi][d];
    if (lane == 0)
        #pragma unroll
        for (int qi = 0; qi < NQ; qi++) sm_se[w][qi] = se[qi];
    __syncthreads();

    // block-level tree sum, then one clean store per element (no atomics)
    float* part = g_part + (size_t)split * NOUT + bh * NQ * DIM;
    for (int o = tid; o < NQ * DIM; o += NTHREADS) {
        float sum = 0.f;
        #pragma unroll
        for (int ww = 0; ww < 8; ww++) sum += sm[ww][o];
        part[o] = sum;
    }
    if (tid < NQ) {
        float sum = 0.f;
        #pragma unroll
        for (int ww = 0; ww < 8; ww++) sum += sm_se[ww][tid];
        g_pse[split * NLSE + bh * NQ + tid] = sum;
    }
}

// Output: fp32 buffer, out_size elements.
//   [0, 65536):      out — fp32 double-rounded through fp16 (ref casts to fp16)
//   [65536, 66048):  lse (fp32)
//   [66048, out_size): zeros (harness poisons with 0xAA)
__global__ void finalize_kernel(float* out, int out_elems) {
    int i = blockIdx.x * blockDim.x + threadIdx.x;
    if (i < NOUT) {
        int bhq = i >> 7;
        float a = 0.f, s = 0.f;
        #pragma unroll
        for (int sp = 0; sp < NSPLIT; sp++) {
            a += g_part[sp * NOUT + i];
            s += g_pse[sp * NLSE + bhq];
        }
        out[i] = __half2float(__float2half(a / s));
    } else if (i < NOUT + NLSE) {
        int bhq = i - NOUT;
        float s = 0.f;
        #pragma unroll
        for (int sp = 0; sp < NSPLIT; sp++) s += g_pse[sp * NLSE + bhq];
        out[i] = logf(s);
    } else if (i < out_elems) {
        out[i] = 0.0f;
    }
}

extern "C" void kernel_launch(void* const* d_in, const int* in_sizes, int n_in,
                              void* d_out, int out_size) {
    // Proven (R9/R10): fp32 inputs, dict ordering:
    //   q, k_A, v_A, k_B_gpu(zeros), v_B_gpu(zeros), k_B_host, v_B_host
    const float* q  = reinterpret_cast<const float*>(d_in[0]);
    const float* kA = reinterpret_cast<const float*>(d_in[1]);
    const float* vA = reinterpret_cast<const float*>(d_in[2]);
    const float* kB = reinterpret_cast<const float*>(d_in[5]);
    const float* vB = reinterpret_cast<const float*>(d_in[6]);

    dim3 grid(NBH, NSPLIT);
    attn_f32<<<grid, NTHREADS>>>(q, kA, vA, kB, vB);

    int full = NOUT + NLSE;
    int cover = out_size > full ? out_size : full;
    finalize_kernel<<<(cover + 255) / 256, 256>>>(
        reinterpret_cast<float*>(d_out), out_size);
}